// round 10
// baseline (speedup 1.0000x reference)
#include <cuda_runtime.h>

// Problem constants
#define BB 16
#define NL 4097          // x0 rows per batch
#define NM 1024          // p_m rows
#define DS 256
#define DM 512
#define DL 1024
#define NKV 4098         // cls + NL
#define NCHUNK 64        // big covers 64*64 = 4096 rows; row 4096 handled in tail
#define MCH 32           // m-chunks for transposed gemv
#define TGRID 148        // persistent grid (co-resident)

// ---------------- device scratch ----------------
__device__ float g_csp  [BB*DM];
__device__ float g_q1   [BB*DM];
__device__ float g_qk1  [BB*DM];
__device__ float g_cmp  [BB*DL];
__device__ float g_q2   [BB*DL];
__device__ float g_qk2  [BB*DL];
__device__ float g_att1s[BB*(NM+1)];   // unnormalized exp(score/22)
__device__ float g_a1p  [BB*NKV];
__device__ float g_PE   [BB*NCHUNK*DL];
__device__ float g_PA   [BB*NCHUNK*DL];
__device__ float g_PZ   [BB*NCHUNK];
__device__ float g_eps  [BB*3];        // ecls, wl2, zsh per batch
__device__ float g_u    [BB*DL];
__device__ float g_outv [BB*DL];
__device__ float g_gs   [BB*DS];
__device__ float g_part1[MCH*BB*DM];
__device__ float g_part2[MCH*BB*DL];
__device__ unsigned g_gbar[16];        // monotone grid-barrier counters (replay-safe)

// ---------------- grid barrier (monotone counter; never reset) ----------------
__device__ __forceinline__ void grid_barrier(int slot)
{
    __syncthreads();
    __threadfence();
    __syncthreads();
    if (threadIdx.x == 0) {
        unsigned arr = atomicAdd(&g_gbar[slot], 1u) + 1u;
        unsigned tgt = ((arr + TGRID - 1u) / TGRID) * TGRID;
        while (*(volatile unsigned*)&g_gbar[slot] < tgt) { }
        __threadfence();
    }
    __syncthreads();
}

// ---------------- multi-batch GEMV body: Y[b,m] = bias[m] + W[m,:]·X[b,:] ----------------
__device__ __forceinline__ void gemvA_body(int mblk, const float* __restrict__ W,
                                           const float* __restrict__ X, int ldx4,
                                           const float* __restrict__ bias,
                                           float* __restrict__ Y, int M, int D)
{
    int m = mblk * 8 + (threadIdx.x >> 5);
    int lane = threadIdx.x & 31;
    if (m >= M) return;
    const float4* w4 = (const float4*)(W + (size_t)m * D);
    const float4* x4 = (const float4*)X;
    int D4 = D >> 2;
    float acc[BB];
#pragma unroll
    for (int b = 0; b < BB; b++) acc[b] = 0.f;
    for (int f = lane; f < D4; f += 32) {
        float4 w = w4[f];
#pragma unroll
        for (int b = 0; b < BB; b++) {
            float4 x = x4[(size_t)b * ldx4 + f];
            acc[b] += w.x*x.x + w.y*x.y + w.z*x.z + w.w*x.w;
        }
    }
#pragma unroll
    for (int b = 0; b < BB; b++) {
        float v = acc[b];
#pragma unroll
        for (int o = 16; o; o >>= 1) v += __shfl_xor_sync(~0u, v, o);
        if (lane == 0) Y[(size_t)b * M + m] = v + (bias ? bias[m] : 0.f);
    }
}

// ---------------- transposed GEMV partial body (smem passed in) ----------------
__device__ __forceinline__ void gemvB_body(int dx, int my, const float* __restrict__ W,
                                           const float* __restrict__ X,
                                           float* __restrict__ part, int M, int D,
                                           float* q /* smem >= BB*32 */)
{
    int d = dx * 256 + threadIdx.x;
    int rows = M / MCH;                 // 16 or 32
    int m0 = my * rows;
    for (int idx = threadIdx.x; idx < BB * rows; idx += 256) {
        int bb = idx / rows, mm = idx - bb * rows;
        q[bb * rows + mm] = X[(size_t)bb * M + m0 + mm];
    }
    __syncthreads();
    float acc[BB];
#pragma unroll
    for (int b = 0; b < BB; b++) acc[b] = 0.f;
    for (int mm = 0; mm < rows; mm++) {
        float w = W[(size_t)(m0 + mm) * D + d];
#pragma unroll
        for (int b = 0; b < BB; b++) acc[b] += w * q[b * rows + mm];
    }
#pragma unroll
    for (int b = 0; b < BB; b++)
        part[((size_t)my * BB + b) * D + d] = acc[b];
}

__device__ __forceinline__ void gemvBred_body(int t, const float* __restrict__ part,
                                              float* __restrict__ Y, int D)
{
    int b = t / D, d = t - b * D;
    float acc = 0.f;
#pragma unroll
    for (int c = 0; c < MCH; c++) acc += part[((size_t)c * BB + b) * D + d];
    Y[t] = acc;
}

// ================= qkchain1: csp -> q1 -> qk1 partials -> qk1 reduce =================
__global__ __launch_bounds__(256) void qkchain1_kernel(
    const float* __restrict__ f_s_w, const float* __restrict__ x2,
    const float* __restrict__ f_s_b, const float* __restrict__ Wq1,
    const float* __restrict__ Wk1)
{
    __shared__ float q[BB * 32];
    int bid = blockIdx.x;
    if (bid < 64) gemvA_body(bid, f_s_w, x2, (NL * DS) / 4, f_s_b, g_csp, DM, DS);
    grid_barrier(0);
    if (bid < 64) gemvA_body(bid, Wq1, g_csp, DM / 4, nullptr, g_q1, DM, DM);
    grid_barrier(1);
    if (bid < 64) gemvB_body(bid & 1, bid >> 1, Wk1, g_q1, g_part1, DM, DM, q);
    grid_barrier(2);
    if (bid < 32) gemvBred_body(bid * 256 + threadIdx.x, g_part1, g_qk1, DM);
}

// ================= qkchain2: cmp -> q2 -> qk2 partials -> qk2 reduce =================
__global__ __launch_bounds__(256) void qkchain2_kernel(
    const float* __restrict__ f_m_w, const float* __restrict__ x1,
    const float* __restrict__ f_m_b, const float* __restrict__ Wq2,
    const float* __restrict__ Wk2)
{
    __shared__ float q[BB * 32];
    int bid = blockIdx.x;
    if (bid < 128) gemvA_body(bid, f_m_w, x1, ((NM + 1) * DM) / 4, f_m_b, g_cmp, DL, DM);
    grid_barrier(3);
    if (bid < 128) gemvA_body(bid, Wq2, g_cmp, DL / 4, nullptr, g_q2, DL, DL);
    grid_barrier(4);
    if (bid < 128) gemvB_body(bid & 3, bid >> 2, Wk2, g_q2, g_part2, DL, DL, q);
    grid_barrier(5);
    if (bid < 64) gemvBred_body(bid * 256 + threadIdx.x, g_part2, g_qk2, DL);
}

// ---------------- score1e: p_m scores -> unnormalized exp; blocks >= 512 do cls ----------------
__global__ __launch_bounds__(256) void score1e_kernel(const float* __restrict__ x1)
{
    int blk = blockIdx.x;
    int warp = threadIdx.x >> 5, lane = threadIdx.x & 31;
    if (blk < 512) {
        int gw = blk * 8 + warp;
        int rr = gw * 4;
        int b = rr >> 10, k0 = rr & 1023;
        const float4* qk = (const float4*)(g_qk1 + (size_t)b * DM);
        float4 q[4];
#pragma unroll
        for (int j = 0; j < 4; j++) q[j] = qk[lane + 32 * j];
#pragma unroll
        for (int i = 0; i < 4; i++) {
            const float4* row = (const float4*)(x1 + ((size_t)b * (NM + 1) + 1 + k0 + i) * DM);
            float s = 0.f;
#pragma unroll
            for (int j = 0; j < 4; j++) {
                float4 v = __ldcs(row + lane + 32 * j);
                s += v.x*q[j].x + v.y*q[j].y + v.z*q[j].z + v.w*q[j].w;
            }
#pragma unroll
            for (int o = 16; o; o >>= 1) s += __shfl_xor_sync(~0u, s, o);
            if (!lane) g_att1s[(size_t)b * (NM + 1) + 1 + k0 + i] = __expf(s * (1.f / 22.f));
        }
    } else {
        int b = (blk - 512) * 8 + warp;   // blocks 512,513 -> batches 0..15
        const float4* c4 = (const float4*)(g_csp + (size_t)b * DM);
        const float4* q4 = (const float4*)(g_qk1 + (size_t)b * DM);
        float p = 0.f;
#pragma unroll
        for (int j = 0; j < 4; j++) {
            float4 cc = c4[lane + 32 * j];
            float4 qq = q4[lane + 32 * j];
            p += cc.x*qq.x + cc.y*qq.y + cc.z*qq.z + cc.w*qq.w;
        }
#pragma unroll
        for (int o = 16; o; o >>= 1) p += __shfl_xor_sync(~0u, p, o);
        if (!lane) g_att1s[(size_t)b * (NM + 1)] = __expf(p * (1.f / 22.f));
    }
}

// ---------------- projZ: inline 1/Z + projection, all 16 batches per block ----------------
__global__ __launch_bounds__(256) void projZ_kernel(
    const float* __restrict__ proj_w, const float* __restrict__ proj_b)
{
    extern __shared__ float sm[];           // att [BB*(NM+1)] then zinv[16]
    float* att = sm;
    float* zs  = sm + BB * (NM + 1);
    int warp = threadIdx.x >> 5, lane = threadIdx.x & 31;
    for (int idx = threadIdx.x; idx < BB * (NM + 1); idx += 256) {
        int bb = idx / (NM + 1), i = idx - bb * (NM + 1);
        att[idx] = g_att1s[(size_t)bb * (NM + 1) + i];
    }
    __syncthreads();
#pragma unroll
    for (int h = 0; h < 2; h++) {           // warp w -> batches w, w+8 (deterministic)
        int bb = warp + 8 * h;
        float z = 0.f;
        for (int i = lane; i < NM + 1; i += 32) z += att[bb * (NM + 1) + i];
#pragma unroll
        for (int o = 16; o; o >>= 1) z += __shfl_xor_sync(~0u, z, o);
        if (!lane) zs[bb] = 1.f / z;
    }
    __syncthreads();
    int j = blockIdx.x * 8 + warp;
    if (j >= NKV) return;
    const float* wrow = proj_w + (size_t)j * (NM + 1);
    float acc[BB];
#pragma unroll
    for (int bb = 0; bb < BB; bb++) acc[bb] = 0.f;
    for (int i = lane; i < NM + 1; i += 32) {
        float w = __ldcs(wrow + i);
#pragma unroll
        for (int bb = 0; bb < BB; bb++) acc[bb] += w * att[bb * (NM + 1) + i];
    }
#pragma unroll
    for (int bb = 0; bb < BB; bb++) {
        float v = acc[bb];
#pragma unroll
        for (int o = 16; o; o >>= 1) v += __shfl_xor_sync(~0u, v, o);
        if (!lane) g_a1p[(size_t)bb * NKV + j] = v * zs[bb] + proj_b[j];
    }
}

// ---------------- big: fused x0 pass (proven) ----------------
__global__ __launch_bounds__(256) void big_kernel(const float* __restrict__ x0)
{
    int b = blockIdx.y, chunk = blockIdx.x;
    int t = threadIdx.x, warp = t >> 5, lane = t & 31;
    __shared__ float4 qk2s[256];
    __shared__ float4 Es[256], As[256];
    __shared__ float Zs[8];
    qk2s[t] = ((const float4*)(g_qk2 + (size_t)b * DL))[t];
    Es[t] = make_float4(0.f, 0.f, 0.f, 0.f);
    As[t] = make_float4(0.f, 0.f, 0.f, 0.f);
    __syncthreads();

    float4 aE[8], aA[8];
#pragma unroll
    for (int j = 0; j < 8; j++) { aE[j] = make_float4(0,0,0,0); aA[j] = make_float4(0,0,0,0); }
    float zacc = 0.f;
    int k0 = chunk * 64 + warp;
#pragma unroll 2
    for (int rr = 0; rr < 8; rr++) {
        int k = k0 + rr * 8;
        const float4* row = (const float4*)(x0 + ((size_t)b * NL + k) * DL);
        float4 v[8];
#pragma unroll
        for (int j = 0; j < 8; j++) v[j] = __ldcs(row + lane + 32 * j);
        float s = 0.f;
#pragma unroll
        for (int j = 0; j < 8; j++) {
            float4 q = qk2s[lane + 32 * j];
            s += v[j].x*q.x + v[j].y*q.y + v[j].z*q.z + v[j].w*q.w;
        }
#pragma unroll
        for (int o = 16; o; o >>= 1) s += __shfl_xor_sync(~0u, s, o);
        float w2 = __expf(s * (1.f / 32.f));
        float w1 = g_a1p[(size_t)b * NKV + k + 1];
        zacc += w2;
#pragma unroll
        for (int j = 0; j < 8; j++) {
            aE[j].x += w2 * v[j].x; aE[j].y += w2 * v[j].y; aE[j].z += w2 * v[j].z; aE[j].w += w2 * v[j].w;
            aA[j].x += w1 * v[j].x; aA[j].y += w1 * v[j].y; aA[j].z += w1 * v[j].z; aA[j].w += w1 * v[j].w;
        }
    }
    for (int w = 0; w < 8; w++) {
        if (warp == w) {
#pragma unroll
            for (int j = 0; j < 8; j++) {
                int idx = lane + 32 * j;
                float4 e = Es[idx];
                e.x += aE[j].x; e.y += aE[j].y; e.z += aE[j].z; e.w += aE[j].w;
                Es[idx] = e;
                float4 a = As[idx];
                a.x += aA[j].x; a.y += aA[j].y; a.z += aA[j].z; a.w += aA[j].w;
                As[idx] = a;
            }
            if (lane == 0) Zs[w] = zacc;
        }
        __syncthreads();
    }
    ((float4*)(g_PE + ((size_t)b * NCHUNK + chunk) * DL))[t] = Es[t];
    ((float4*)(g_PA + ((size_t)b * NCHUNK + chunk) * DL))[t] = As[t];
    if (t == 0) {
        float z = 0.f;
#pragma unroll
        for (int w = 0; w < 8; w++) z += Zs[w];
        g_PZ[b * NCHUNK + chunk] = z;
    }
}

// ---------------- tail_small: scalars -> u -> Wv·u -> gs (all phases <=148 blocks) ----------------
__global__ __launch_bounds__(256) void tail_small_kernel(
    const float* __restrict__ x0, const float* __restrict__ Wv,
    const float* __restrict__ gs_w, const float* __restrict__ gs_b)
{
    __shared__ float red[256];
    int bid = blockIdx.x, tid = threadIdx.x;

    // P0: per-batch scalars (blocks 0..15)
    if (bid < BB) {
        int b = bid;
        float p1 = 0.f, p2 = 0.f;
#pragma unroll
        for (int i = 0; i < 4; i++) {
            int d = tid + 256 * i;
            float qk = g_qk2[b * DL + d];
            p1 += g_cmp[b * DL + d] * qk;
            p2 += x0[((size_t)b * NL + NL - 1) * DL + d] * qk;
        }
        red[tid] = p1; __syncthreads();
        for (int s = 128; s; s >>= 1) { if (tid < s) red[tid] += red[tid + s]; __syncthreads(); }
        float d1 = red[0]; __syncthreads();
        red[tid] = p2; __syncthreads();
        for (int s = 128; s; s >>= 1) { if (tid < s) red[tid] += red[tid + s]; __syncthreads(); }
        float d2 = red[0]; __syncthreads();
        red[tid] = (tid < NCHUNK) ? g_PZ[b * NCHUNK + tid] : 0.f; __syncthreads();
        for (int s = 128; s; s >>= 1) { if (tid < s) red[tid] += red[tid + s]; __syncthreads(); }
        if (tid == 0) {
            float ecls = __expf(d1 * (1.f / 32.f));
            float wl2  = __expf(d2 * (1.f / 32.f));
            g_eps[b * 3 + 0] = ecls;
            g_eps[b * 3 + 1] = wl2;
            g_eps[b * 3 + 2] = ecls + wl2 + red[0];
        }
    }
    grid_barrier(6);

    // P1: u[b,d] (16384 elements)
    for (int e = bid * 256 + tid; e < BB * DL; e += TGRID * 256) {
        int b = e >> 10, d = e & 1023;
        float cmp = g_cmp[e];
        float xlast = x0[((size_t)b * NL + NL - 1) * DL + d];
        float ecls = g_eps[b * 3 + 0], wl2 = g_eps[b * 3 + 1], zsh = g_eps[b * 3 + 2];
        float esum = 0.f, asum = 0.f;
#pragma unroll 4
        for (int c = 0; c < NCHUNK; c++) {
            esum += g_PE[((size_t)b * NCHUNK + c) * DL + d];
            asum += g_PA[((size_t)b * NCHUNK + c) * DL + d];
        }
        float a1p0 = g_a1p[(size_t)b * NKV];
        float a1pl = g_a1p[(size_t)b * NKV + NKV - 1];
        esum += wl2 * xlast;
        asum += a1pl * xlast;
        g_u[e] = 0.3f * (a1p0 * cmp + asum) + 0.7f * (ecls * cmp + esum) / zsh;
    }
    grid_barrier(7);

    // P2: outv = Wv · u (128 tasks)
    if (bid < 128) gemvA_body(bid, Wv, g_u, DL / 4, nullptr, g_outv, DL, DL);
    grid_barrier(8);

    // P3: gs = gs_w · outv + gs_b (32 tasks)
    if (bid < 32) gemvA_body(bid, gs_w, g_outv, DL / 4, gs_b, g_gs, DS, DL);
}

// ---------------- broadcast g_s to all 4097 output rows (2064 blocks, proven) ----------------
__global__ __launch_bounds__(256) void write_kernel(float* __restrict__ out)
{
    int b = blockIdx.y;
    int g = threadIdx.x >> 6, l = threadIdx.x & 63;
    float4 val = ((const float4*)(g_gs + b * DS))[l];
    int base = blockIdx.x * 32;
    float4* ob = (float4*)out + (size_t)b * NL * 64;
    int lim = base + 32; if (lim > NL) lim = NL;
    for (int r = base + g; r < lim; r += 4)
        __stcs(ob + (size_t)r * 64 + l, val);
}

// ---------------- launch: 7 nodes, fork-join 2 streams ----------------
extern "C" void kernel_launch(void* const* d_in, const int* in_sizes, int n_in,
                              void* d_out, int out_size)
{
    const float* x0     = (const float*)d_in[0];
    const float* x1     = (const float*)d_in[1];
    const float* x2     = (const float*)d_in[2];
    const float* f_s_w  = (const float*)d_in[3];
    const float* f_s_b  = (const float*)d_in[4];
    const float* f_m_w  = (const float*)d_in[5];
    const float* f_m_b  = (const float*)d_in[6];
    const float* Wq1    = (const float*)d_in[7];
    const float* Wk1    = (const float*)d_in[8];
    const float* Wq2    = (const float*)d_in[9];
    const float* Wk2    = (const float*)d_in[10];
    const float* Wv     = (const float*)d_in[11];
    const float* proj_w = (const float*)d_in[12];
    const float* proj_b = (const float*)d_in[13];
    const float* gs_w   = (const float*)d_in[14];
    const float* gs_b   = (const float*)d_in[15];

    static cudaStream_t s1 = nullptr, s2 = nullptr;
    static cudaEvent_t evr = nullptr, ev1 = nullptr, ev2 = nullptr;
    if (!s1) {
        cudaStreamCreateWithFlags(&s1, cudaStreamNonBlocking);
        cudaStreamCreateWithFlags(&s2, cudaStreamNonBlocking);
        cudaEventCreateWithFlags(&evr, cudaEventDisableTiming);
        cudaEventCreateWithFlags(&ev1, cudaEventDisableTiming);
        cudaEventCreateWithFlags(&ev2, cudaEventDisableTiming);
        cudaFuncSetAttribute(projZ_kernel, cudaFuncAttributeMaxDynamicSharedMemorySize,
                             (BB * (NM + 1) + 16) * 4);
    }

    // fork
    cudaEventRecord(evr, 0);
    cudaStreamWaitEvent(s1, evr, 0);
    cudaStreamWaitEvent(s2, evr, 0);

    // Branch 1: qkchain1 -> score1e -> projZ
    qkchain1_kernel<<<TGRID, 256, 0, s1>>>(f_s_w, x2, f_s_b, Wq1, Wk1);
    score1e_kernel<<<514, 256, 0, s1>>>(x1);
    projZ_kernel<<<(NKV + 7) / 8, 256, (BB * (NM + 1) + 16) * 4, s1>>>(proj_w, proj_b);

    // Branch 2: qkchain2
    qkchain2_kernel<<<TGRID, 256, 0, s2>>>(f_m_w, x1, f_m_b, Wq2, Wk2);

    // join
    cudaEventRecord(ev1, s1);
    cudaEventRecord(ev2, s2);
    cudaStreamWaitEvent(0, ev1, 0);
    cudaStreamWaitEvent(0, ev2, 0);

    // main chain
    big_kernel<<<dim3(NCHUNK, BB), 256>>>(x0);
    tail_small_kernel<<<TGRID, 256>>>(x0, Wv, gs_w, gs_b);
    write_kernel<<<dim3((NL + 31) / 32, BB), 256>>>((float*)d_out);
}

// round 11
// speedup vs baseline: 1.0495x; 1.0495x over previous
#include <cuda_runtime.h>

// Problem constants
#define BB 16
#define NL 4097          // x0 rows per batch
#define NM 1024          // p_m rows
#define DS 256
#define DM 512
#define DL 1024
#define NKV 4098         // cls + NL
#define NCHUNK 64        // big covers 64*64 = 4096 rows; row 4096 handled in u_kernel
#define MCH 32           // m-chunks for transposed gemv

// PDL device hooks (sm_90+): wait for programmatic predecessor / release dependents
#define GRID_WAIT()       asm volatile("griddepcontrol.wait;" ::: "memory")
#define GRID_LAUNCH_DEP() asm volatile("griddepcontrol.launch_dependents;" ::: "memory")

// ---------------- device scratch ----------------
__device__ float g_csp  [BB*DM];
__device__ float g_q1   [BB*DM];
__device__ float g_qk1  [BB*DM];
__device__ float g_cmp  [BB*DL];
__device__ float g_q2   [BB*DL];
__device__ float g_qk2  [BB*DL];
__device__ float g_sc1  [BB*(NM+1)];
__device__ float g_att1s[BB*(NM+1)];
__device__ float g_a1p  [BB*NKV];
__device__ float g_PE   [BB*NCHUNK*DL];
__device__ float g_PA   [BB*NCHUNK*DL];
__device__ float g_PZ   [BB*NCHUNK];
__device__ float g_u    [BB*DL];
__device__ float g_outv [BB*DL];
__device__ float g_gs   [BB*DS];
__device__ float g_part1[MCH*BB*DM];
__device__ float g_part2[MCH*BB*DL];

// ---------------- multi-batch GEMV: Y[b,m] = bias[m] + W[m,:]·X[b,:] ----------------
__global__ __launch_bounds__(256) void gemvA_kernel(
    const float* __restrict__ W, const float* __restrict__ X, int ldx4,
    const float* __restrict__ bias, float* __restrict__ Y, int M, int D)
{
    GRID_WAIT();
    int m = blockIdx.x * 8 + (threadIdx.x >> 5);
    int lane = threadIdx.x & 31;
    if (m < M) {
        const float4* w4 = (const float4*)(W + (size_t)m * D);
        const float4* x4 = (const float4*)X;
        int D4 = D >> 2;
        float acc[BB];
#pragma unroll
        for (int b = 0; b < BB; b++) acc[b] = 0.f;
        for (int f = lane; f < D4; f += 32) {
            float4 w = w4[f];
#pragma unroll
            for (int b = 0; b < BB; b++) {
                float4 x = x4[(size_t)b * ldx4 + f];
                acc[b] += w.x*x.x + w.y*x.y + w.z*x.z + w.w*x.w;
            }
        }
#pragma unroll
        for (int b = 0; b < BB; b++) {
            float v = acc[b];
#pragma unroll
            for (int o = 16; o; o >>= 1) v += __shfl_xor_sync(~0u, v, o);
            if (lane == 0) Y[(size_t)b * M + m] = v + (bias ? bias[m] : 0.f);
        }
    }
    GRID_LAUNCH_DEP();
}

// ---------------- transposed GEMV partials: part[my][b][d] ----------------
__global__ __launch_bounds__(256) void gemvB_kernel(
    const float* __restrict__ W, const float* __restrict__ X,
    float* __restrict__ part, int M, int D)
{
    GRID_WAIT();
    int d = blockIdx.x * 256 + threadIdx.x;
    int rows = M / MCH;                 // 16 or 32
    int m0 = blockIdx.y * rows;
    __shared__ float q[BB * 32];
    for (int idx = threadIdx.x; idx < BB * rows; idx += 256) {
        int bb = idx / rows, mm = idx - bb * rows;
        q[bb * rows + mm] = X[(size_t)bb * M + m0 + mm];
    }
    __syncthreads();
    float acc[BB];
#pragma unroll
    for (int b = 0; b < BB; b++) acc[b] = 0.f;
    for (int mm = 0; mm < rows; mm++) {
        float w = W[(size_t)(m0 + mm) * D + d];
#pragma unroll
        for (int b = 0; b < BB; b++) acc[b] += w * q[b * rows + mm];
    }
#pragma unroll
    for (int b = 0; b < BB; b++)
        part[((size_t)blockIdx.y * BB + b) * D + d] = acc[b];
    GRID_LAUNCH_DEP();
}

__global__ __launch_bounds__(256) void gemvBred_kernel(
    const float* __restrict__ part, float* __restrict__ Y, int D)
{
    GRID_WAIT();
    int t = blockIdx.x * 256 + threadIdx.x;
    int b = t / D, d = t - b * D;
    float acc = 0.f;
#pragma unroll
    for (int c = 0; c < MCH; c++) acc += part[((size_t)c * BB + b) * D + d];
    Y[t] = acc;
    GRID_LAUNCH_DEP();
}

// ---------------- att1 scores over p_m: 4 rows per warp ----------------
__global__ __launch_bounds__(256) void score1_kernel(const float* __restrict__ x1)
{
    GRID_WAIT();
    int gw = (blockIdx.x * 256 + threadIdx.x) >> 5;
    int lane = threadIdx.x & 31;
    int rr = gw * 4;
    int b = rr >> 10, k0 = rr & 1023;
    const float4* qk = (const float4*)(g_qk1 + (size_t)b * DM);
    float4 q[4];
#pragma unroll
    for (int j = 0; j < 4; j++) q[j] = qk[lane + 32 * j];
#pragma unroll
    for (int i = 0; i < 4; i++) {
        const float4* row = (const float4*)(x1 + ((size_t)b * (NM + 1) + 1 + k0 + i) * DM);
        float s = 0.f;
#pragma unroll
        for (int j = 0; j < 4; j++) {
            float4 v = __ldcs(row + lane + 32 * j);
            s += v.x*q[j].x + v.y*q[j].y + v.z*q[j].z + v.w*q[j].w;
        }
#pragma unroll
        for (int o = 16; o; o >>= 1) s += __shfl_xor_sync(~0u, s, o);
        if (!lane) g_sc1[(size_t)b * (NM + 1) + 1 + k0 + i] = s * (1.f / 22.f);
    }
    GRID_LAUNCH_DEP();
}

// ---------------- softmax att1 (scores O(0.1) -> no max subtraction needed) ----------------
__global__ __launch_bounds__(256) void soft1_kernel()
{
    GRID_WAIT();
    int b = blockIdx.x, t = threadIdx.x;
    __shared__ float red[256];
    __shared__ float ex[NM + 1];
    __shared__ float s0sh;
    float p = 0.f;
    for (int i = t; i < DM; i += 256) p += g_csp[b * DM + i] * g_qk1[b * DM + i];
    red[t] = p; __syncthreads();
    for (int s = 128; s; s >>= 1) { if (t < s) red[t] += red[t + s]; __syncthreads(); }
    if (t == 0) s0sh = red[0] * (1.f / 22.f);
    __syncthreads();
    float zp = 0.f;
    for (int i = t; i < NM + 1; i += 256) {
        float s = (i == 0) ? s0sh : g_sc1[b * (NM + 1) + i];
        float e = __expf(s);
        ex[i] = e; zp += e;
    }
    red[t] = zp; __syncthreads();
    for (int s = 128; s; s >>= 1) { if (t < s) red[t] += red[t + s]; __syncthreads(); }
    float inv = 1.f / red[0];
    for (int i = t; i < NM + 1; i += 256) g_att1s[b * (NM + 1) + i] = ex[i] * inv;
    GRID_LAUNCH_DEP();
}

// ---------------- att1 projection: single pass over proj_w, all 16 batches ----------------
__global__ __launch_bounds__(256) void proj_kernel(
    const float* __restrict__ proj_w, const float* __restrict__ proj_b)
{
    GRID_WAIT();
    extern __shared__ float att[];             // [BB * (NM+1)] = 65568 B
    for (int idx = threadIdx.x; idx < BB * (NM + 1); idx += 256) {
        int bb = idx / (NM + 1), i = idx - bb * (NM + 1);
        att[idx] = g_att1s[(size_t)bb * (NM + 1) + i];
    }
    __syncthreads();
    int j = blockIdx.x * 8 + (threadIdx.x >> 5);
    int lane = threadIdx.x & 31;
    if (j < NKV) {
        const float* wrow = proj_w + (size_t)j * (NM + 1);
        float acc[BB];
#pragma unroll
        for (int bb = 0; bb < BB; bb++) acc[bb] = 0.f;
        for (int i = lane; i < NM + 1; i += 32) {
            float w = __ldcs(wrow + i);
#pragma unroll
            for (int bb = 0; bb < BB; bb++) acc[bb] += w * att[bb * (NM + 1) + i];
        }
#pragma unroll
        for (int bb = 0; bb < BB; bb++) {
            float v = acc[bb];
#pragma unroll
            for (int o = 16; o; o >>= 1) v += __shfl_xor_sync(~0u, v, o);
            if (!lane) g_a1p[(size_t)bb * NKV + j] = v + proj_b[j];
        }
    }
    GRID_LAUNCH_DEP();
}

// ---------------- fused x0 pass: 64 full rows per chunk ----------------
__global__ __launch_bounds__(256) void big_kernel(const float* __restrict__ x0)
{
    GRID_WAIT();
    int b = blockIdx.y, chunk = blockIdx.x;
    int t = threadIdx.x, warp = t >> 5, lane = t & 31;
    __shared__ float4 qk2s[256];
    __shared__ float4 Es[256], As[256];
    __shared__ float Zs[8];
    qk2s[t] = ((const float4*)(g_qk2 + (size_t)b * DL))[t];
    Es[t] = make_float4(0.f, 0.f, 0.f, 0.f);
    As[t] = make_float4(0.f, 0.f, 0.f, 0.f);
    __syncthreads();

    float4 aE[8], aA[8];
#pragma unroll
    for (int j = 0; j < 8; j++) { aE[j] = make_float4(0,0,0,0); aA[j] = make_float4(0,0,0,0); }
    float zacc = 0.f;
    int k0 = chunk * 64 + warp;
#pragma unroll 2
    for (int rr = 0; rr < 8; rr++) {
        int k = k0 + rr * 8;
        const float4* row = (const float4*)(x0 + ((size_t)b * NL + k) * DL);
        float4 v[8];
#pragma unroll
        for (int j = 0; j < 8; j++) v[j] = __ldcs(row + lane + 32 * j);
        float s = 0.f;
#pragma unroll
        for (int j = 0; j < 8; j++) {
            float4 q = qk2s[lane + 32 * j];
            s += v[j].x*q.x + v[j].y*q.y + v[j].z*q.z + v[j].w*q.w;
        }
#pragma unroll
        for (int o = 16; o; o >>= 1) s += __shfl_xor_sync(~0u, s, o);
        float w2 = __expf(s * (1.f / 32.f));
        float w1 = g_a1p[(size_t)b * NKV + k + 1];
        zacc += w2;
#pragma unroll
        for (int j = 0; j < 8; j++) {
            aE[j].x += w2 * v[j].x; aE[j].y += w2 * v[j].y; aE[j].z += w2 * v[j].z; aE[j].w += w2 * v[j].w;
            aA[j].x += w1 * v[j].x; aA[j].y += w1 * v[j].y; aA[j].z += w1 * v[j].z; aA[j].w += w1 * v[j].w;
        }
    }
    for (int w = 0; w < 8; w++) {
        if (warp == w) {
#pragma unroll
            for (int j = 0; j < 8; j++) {
                int idx = lane + 32 * j;
                float4 e = Es[idx];
                e.x += aE[j].x; e.y += aE[j].y; e.z += aE[j].z; e.w += aE[j].w;
                Es[idx] = e;
                float4 a = As[idx];
                a.x += aA[j].x; a.y += aA[j].y; a.z += aA[j].z; a.w += aA[j].w;
                As[idx] = a;
            }
            if (lane == 0) Zs[w] = zacc;
        }
        __syncthreads();
    }
    ((float4*)(g_PE + ((size_t)b * NCHUNK + chunk) * DL))[t] = Es[t];
    ((float4*)(g_PA + ((size_t)b * NCHUNK + chunk) * DL))[t] = As[t];
    if (t == 0) {
        float z = 0.f;
#pragma unroll
        for (int w = 0; w < 8; w++) z += Zs[w];
        g_PZ[b * NCHUNK + chunk] = z;
    }
    GRID_LAUNCH_DEP();
}

// ---------------- combine partials + cls row + last p_l row -> u[b,d] ----------------
__global__ __launch_bounds__(1024) void u_kernel(const float* __restrict__ x0)
{
    GRID_WAIT();
    int b = blockIdx.x, d = threadIdx.x;
    __shared__ float red[1024];
    __shared__ float zsh, wl2sh;
    float cmp = g_cmp[b * DL + d];
    float qk  = g_qk2[b * DL + d];
    float xlast = x0[((size_t)b * NL + NL - 1) * DL + d];
    red[d] = cmp * qk; __syncthreads();
    for (int s = 512; s; s >>= 1) { if (d < s) red[d] += red[d + s]; __syncthreads(); }
    float ecls = __expf(red[0] * (1.f / 32.f));
    __syncthreads();
    red[d] = xlast * qk; __syncthreads();
    for (int s = 512; s; s >>= 1) { if (d < s) red[d] += red[d + s]; __syncthreads(); }
    if (d == 0) {
        float wl2 = __expf(red[0] * (1.f / 32.f));
        float z = ecls + wl2;
        for (int c = 0; c < NCHUNK; c++) z += g_PZ[b * NCHUNK + c];
        zsh = z; wl2sh = wl2;
    }
    __syncthreads();
    float e = 0.f, a = 0.f;
    for (int c = 0; c < NCHUNK; c++) {
        e += g_PE[((size_t)b * NCHUNK + c) * DL + d];
        a += g_PA[((size_t)b * NCHUNK + c) * DL + d];
    }
    float a1p0 = g_a1p[(size_t)b * NKV];
    float a1pl = g_a1p[(size_t)b * NKV + NKV - 1];
    e += wl2sh * xlast;
    a += a1pl * xlast;
    g_u[b * DL + d] = 0.3f * (a1p0 * cmp + a) + 0.7f * (ecls * cmp + e) / zsh;
    GRID_LAUNCH_DEP();
}

// ---------------- broadcast g_s to all 4097 output rows ----------------
__global__ __launch_bounds__(256) void write_kernel(float* __restrict__ out)
{
    GRID_WAIT();
    int b = blockIdx.y;
    int g = threadIdx.x >> 6, l = threadIdx.x & 63;
    float4 val = ((const float4*)(g_gs + b * DS))[l];
    int base = blockIdx.x * 32;
    float4* ob = (float4*)out + (size_t)b * NL * 64;
    int lim = base + 32; if (lim > NL) lim = NL;
    for (int r = base + g; r < lim; r += 4)
        __stcs(ob + (size_t)r * 64 + l, val);
    GRID_LAUNCH_DEP();
}

// ---------------- PDL launch helper ----------------
static cudaLaunchAttribute g_pdl_attr;

static inline void launch_pdl(const void* fn, dim3 grid, dim3 block, size_t shmem,
                              cudaStream_t st, void** args)
{
    cudaLaunchConfig_t cfg = {};
    cfg.gridDim = grid;
    cfg.blockDim = block;
    cfg.dynamicSmemBytes = shmem;
    cfg.stream = st;
    cfg.attrs = &g_pdl_attr;
    cfg.numAttrs = 1;
    cudaLaunchKernelExC(&cfg, fn, args);
}

// ---------------- launch: R6 fork-join topology + PDL on dependent edges ----------------
extern "C" void kernel_launch(void* const* d_in, const int* in_sizes, int n_in,
                              void* d_out, int out_size)
{
    const float* x0     = (const float*)d_in[0];
    const float* x1     = (const float*)d_in[1];
    const float* x2     = (const float*)d_in[2];
    const float* f_s_w  = (const float*)d_in[3];
    const float* f_s_b  = (const float*)d_in[4];
    const float* f_m_w  = (const float*)d_in[5];
    const float* f_m_b  = (const float*)d_in[6];
    const float* Wq1    = (const float*)d_in[7];
    const float* Wk1    = (const float*)d_in[8];
    const float* Wq2    = (const float*)d_in[9];
    const float* Wk2    = (const float*)d_in[10];
    const float* Wv     = (const float*)d_in[11];
    const float* proj_w = (const float*)d_in[12];
    const float* proj_b = (const float*)d_in[13];
    const float* gs_w   = (const float*)d_in[14];
    const float* gs_b   = (const float*)d_in[15];

    static cudaStream_t s1 = nullptr, s2 = nullptr;
    static cudaEvent_t evr = nullptr, ev1 = nullptr, ev2 = nullptr;
    if (!s1) {
        cudaStreamCreateWithFlags(&s1, cudaStreamNonBlocking);
        cudaStreamCreateWithFlags(&s2, cudaStreamNonBlocking);
        cudaEventCreateWithFlags(&evr, cudaEventDisableTiming);
        cudaEventCreateWithFlags(&ev1, cudaEventDisableTiming);
        cudaEventCreateWithFlags(&ev2, cudaEventDisableTiming);
        cudaFuncSetAttribute(proj_kernel, cudaFuncAttributeMaxDynamicSharedMemorySize,
                             BB * (NM + 1) * 4);
        g_pdl_attr.id = cudaLaunchAttributeProgrammaticStreamSerialization;
        g_pdl_attr.val.programmaticStreamSerializationAllowed = 1;
    }

    float *p_csp, *p_q1, *p_qk1, *p_cmp, *p_q2, *p_qk2, *p_u, *p_outv, *p_gs, *p_part1, *p_part2;
    cudaGetSymbolAddress((void**)&p_csp,   g_csp);
    cudaGetSymbolAddress((void**)&p_q1,    g_q1);
    cudaGetSymbolAddress((void**)&p_qk1,   g_qk1);
    cudaGetSymbolAddress((void**)&p_cmp,   g_cmp);
    cudaGetSymbolAddress((void**)&p_q2,    g_q2);
    cudaGetSymbolAddress((void**)&p_qk2,   g_qk2);
    cudaGetSymbolAddress((void**)&p_u,     g_u);
    cudaGetSymbolAddress((void**)&p_outv,  g_outv);
    cudaGetSymbolAddress((void**)&p_gs,    g_gs);
    cudaGetSymbolAddress((void**)&p_part1, g_part1);
    cudaGetSymbolAddress((void**)&p_part2, g_part2);

    const float* nullb = nullptr;

    // fork
    cudaEventRecord(evr, 0);
    cudaStreamWaitEvent(s1, evr, 0);
    cudaStreamWaitEvent(s2, evr, 0);

    // Branch 1 (att1 chain): csp -> q1 -> qk1 -> score1 -> soft1 -> proj
    gemvA_kernel<<<64, 256, 0, s1>>>(f_s_w, x2, (NL * DS) / 4, f_s_b, p_csp, DM, DS);
    {
        int ld = DM / 4, M = DM, D = DM;
        void* a[] = {(void*)&Wq1, (void*)&p_csp, &ld, (void*)&nullb, (void*)&p_q1, &M, &D};
        launch_pdl((const void*)gemvA_kernel, dim3(64), dim3(256), 0, s1, a);
    }
    {
        int M = DM, D = DM;
        void* a[] = {(void*)&Wk1, (void*)&p_q1, (void*)&p_part1, &M, &D};
        launch_pdl((const void*)gemvB_kernel, dim3(2, MCH), dim3(256), 0, s1, a);
    }
    {
        int D = DM;
        void* a[] = {(void*)&p_part1, (void*)&p_qk1, &D};
        launch_pdl((const void*)gemvBred_kernel, dim3(32), dim3(256), 0, s1, a);
    }
    {
        void* a[] = {(void*)&x1};
        launch_pdl((const void*)score1_kernel, dim3((BB * NM) / 32), dim3(256), 0, s1, a);
    }
    {
        void* a[] = {nullptr};
        launch_pdl((const void*)soft1_kernel, dim3(BB), dim3(256), 0, s1, a);
    }
    {
        void* a[] = {(void*)&proj_w, (void*)&proj_b};
        launch_pdl((const void*)proj_kernel, dim3((NKV + 7) / 8), dim3(256),
                   BB * (NM + 1) * 4, s1, a);
    }

    // Branch 2 (qk2 chain): cmp -> q2 -> qk2
    gemvA_kernel<<<128, 256, 0, s2>>>(f_m_w, x1, ((NM + 1) * DM) / 4, f_m_b, p_cmp, DL, DM);
    {
        int ld = DL / 4, M = DL, D = DL;
        void* a[] = {(void*)&Wq2, (void*)&p_cmp, &ld, (void*)&nullb, (void*)&p_q2, &M, &D};
        launch_pdl((const void*)gemvA_kernel, dim3(128), dim3(256), 0, s2, a);
    }
    {
        int M = DL, D = DL;
        void* a[] = {(void*)&Wk2, (void*)&p_q2, (void*)&p_part2, &M, &D};
        launch_pdl((const void*)gemvB_kernel, dim3(4, MCH), dim3(256), 0, s2, a);
    }
    {
        int D = DL;
        void* a[] = {(void*)&p_part2, (void*)&p_qk2, &D};
        launch_pdl((const void*)gemvBred_kernel, dim3(64), dim3(256), 0, s2, a);
    }

    // join
    cudaEventRecord(ev1, s1);
    cudaEventRecord(ev2, s2);
    cudaStreamWaitEvent(0, ev1, 0);
    cudaStreamWaitEvent(0, ev2, 0);

    // main chain (big launched normally after the event join)
    big_kernel<<<dim3(NCHUNK, BB), 256>>>(x0);
    {
        void* a[] = {(void*)&x0};
        launch_pdl((const void*)u_kernel, dim3(BB), dim3(1024), 0, 0, a);
    }
    {
        int ld = DL / 4, M = DL, D = DL;
        void* a[] = {(void*)&Wv, (void*)&p_u, &ld, (void*)&nullb, (void*)&p_outv, &M, &D};
        launch_pdl((const void*)gemvA_kernel, dim3(128), dim3(256), 0, 0, a);
    }
    {
        int ld = DL / 4, M = DS, D = DL;
        void* a[] = {(void*)&gs_w, (void*)&p_outv, &ld, (void*)&gs_b, (void*)&p_gs, &M, &D};
        launch_pdl((const void*)gemvA_kernel, dim3(32), dim3(256), 0, 0, a);
    }
    {
        float* outp = (float*)d_out;
        void* a[] = {(void*)&outp};
        launch_pdl((const void*)write_kernel, dim3((NL + 31) / 32, BB), dim3(256), 0, 0, a);
    }
}